// round 17
// baseline (speedup 1.0000x reference)
#include <cuda_runtime.h>
#include <cuda_fp16.h>
#include <cstdint>

#define NNODES 8192
#define CDIM   64
#define KNN    9

typedef unsigned long long u64t;
typedef unsigned int u32t;

__device__ float4 g_sq4[NNODES / 4];
__device__ float  g_z[NNODES * CDIM];
__device__ float  g_y[NNODES * CDIM];
__device__ uint4  g_h16[NNODES * 8];
__device__ uint4  g_m16[NNODES * 8];

__device__ __forceinline__ int batch_of(int i) { return (i * 8) / 8191; }
__device__ __forceinline__ float f_ninf() { return __int_as_float(0xff800000); }
// monotone float->u32 (order-preserving incl. negatives/inf)
__device__ __forceinline__ u32t fsort(float w) {
    u32t u = __float_as_uint(w);
    return u ^ ((u32t)((int)u >> 31) | 0x80000000u);
}

__device__ __forceinline__ void fma2(u64t& d, u64t a, u64t b) {
    asm("fma.rn.f32x2 %0, %1, %2, %0;" : "+l"(d) : "l"(a), "l"(b));
}
__device__ __forceinline__ float pairsum(u64t v) {
    float lo, hi;
    asm("mov.b64 {%0, %1}, %2;" : "=f"(lo), "=f"(hi) : "l"(v));
    return lo + hi;
}
__device__ __forceinline__ void cpa16(u32t sa, const void* g) {
    asm volatile("cp.async.cg.shared.global [%0], [%1], 16;" :: "r"(sa), "l"(g));
}
#define CPA_COMMIT() asm volatile("cp.async.commit_group;")
#define CPA_WAIT0()  asm volatile("cp.async.wait_group 0;" ::: "memory")

__device__ __forceinline__ u32t smem_u32(const void* p) {
    u32t a;
    asm("{ .reg .u64 tmp; cvta.to.shared.u64 tmp, %1; cvt.u32.u64 %0, tmp; }"
        : "=r"(a) : "l"(p));
    return a;
}
__device__ __forceinline__ void ldsm4(u32t* r, u32t addr) {
    asm volatile("ldmatrix.sync.aligned.m8n8.x4.shared.b16 {%0,%1,%2,%3}, [%4];"
        : "=r"(r[0]), "=r"(r[1]), "=r"(r[2]), "=r"(r[3]) : "r"(addr));
}
__device__ __forceinline__ void mma16816(float* c, const u32t* a, const u32t* b) {
    asm volatile("mma.sync.aligned.m16n8k16.row.col.f32.f16.f16.f32 "
        "{%0,%1,%2,%3}, {%4,%5,%6,%7}, {%8,%9}, {%0,%1,%2,%3};"
        : "+f"(c[0]), "+f"(c[1]), "+f"(c[2]), "+f"(c[3])
        : "r"(a[0]), "r"(a[1]), "r"(a[2]), "r"(a[3]), "r"(b[0]), "r"(b[1]));
}

// ---------------------------------------------------------------------------
// Fused kernel 1: transpose + fp16 h/m images + sq + both linear GEMMs.
// (verified since round 9)
// ---------------------------------------------------------------------------
#define OFF_S   0
#define OFF_XS  16640
#define OFF_WL  33024
#define OFF_WR  50432
#define PG_SMEM 67840

__global__ void __launch_bounds__(256, 1)
k_pg(const float* __restrict__ x, const float* __restrict__ Wl,
     const float* __restrict__ bl, const float* __restrict__ Wr) {
    extern __shared__ char sm[];
    u32t sb = smem_u32(sm);
    float (*s)[65] = (float(*)[65])(sm + OFF_S);
    float* xs      = (float*)(sm + OFF_XS);
    float (*wl)[68] = (float(*)[68])(sm + OFF_WL);
    float (*wr)[68] = (float(*)[68])(sm + OFF_WR);

    int t = threadIdx.x;
    int tile = blockIdx.x;
    int b = tile >> 4;
    int hw0 = (tile & 15) << 6;
    int w = t & 63, g = t >> 6;

    #pragma unroll
    for (int r = 0; r < 4; r++) {
        int idx = r * 256 + t;
        int o = idx >> 4, c4 = idx & 15;
        cpa16(sb + OFF_WL + o * 272 + c4 * 16, ((const float4*)Wl) + idx);
        cpa16(sb + OFF_WR + o * 272 + c4 * 16, ((const float4*)Wr) + idx);
    }
    CPA_COMMIT();

    #pragma unroll
    for (int r = 0; r < 16; r++) {
        int c = r * 4 + g;
        s[c][w] = x[(((b << 6) + c) << 10) | (hw0 + w)];
    }
    int l = t & 31;
    float bll = bl[l], blh = bl[l + 32];
    __syncthreads();

    int base = (b << 10) + hw0;
    {
        int nl = t >> 2;
        int c0 = (t & 3) << 4;
        #pragma unroll
        for (int gg = 0; gg < 2; gg++) {
            u32t hw4[4], mw4[4];
            #pragma unroll
            for (int pp = 0; pp < 4; pp++) {
                float v0 = s[c0 + gg * 8 + pp * 2][nl];
                float v1 = s[c0 + gg * 8 + pp * 2 + 1][nl];
                __half h0 = __float2half_rn(v0), h1 = __float2half_rn(v1);
                float r0 = v0 - __half2float(h0), r1 = v1 - __half2float(h1);
                __half m0 = __float2half_rn(r0), m1 = __float2half_rn(r1);
                __half2 hh = __halves2half2(h0, h1);
                __half2 mm = __halves2half2(m0, m1);
                hw4[pp] = *(u32t*)&hh;
                mw4[pp] = *(u32t*)&mm;
            }
            int idx = (base + nl) * 8 + (t & 3) * 2 + gg;
            g_h16[idx] = make_uint4(hw4[0], hw4[1], hw4[2], hw4[3]);
            g_m16[idx] = make_uint4(mw4[0], mw4[1], mw4[2], mw4[3]);
        }
    }
    if (t < 64) {
        float acc = 0.f;
        #pragma unroll
        for (int c = 0; c < 64; c++) { float v = s[c][t]; acc = fmaf(v, v, acc); }
        ((float*)g_sq4)[base + t] = acc;
    }
    {
        int nl = t >> 2;
        int c0 = (t & 3) << 4;
        #pragma unroll
        for (int pp = 0; pp < 4; pp++) {
            float4 v = make_float4(s[c0 + pp * 4][nl], s[c0 + pp * 4 + 1][nl],
                                   s[c0 + pp * 4 + 2][nl], s[c0 + pp * 4 + 3][nl]);
            *(float4*)&xs[nl * 64 + c0 + pp * 4] = v;
        }
    }
    CPA_WAIT0();
    __syncthreads();

    int ng = t >> 5;
    u64t az0[8], az1[8], ay0[8], ay1[8];
    #pragma unroll
    for (int i = 0; i < 8; i++) { az0[i] = az1[i] = ay0[i] = ay1[i] = 0ull; }

    #pragma unroll
    for (int c4 = 0; c4 < 16; c4++) {
        ulonglong2 w0 = *(ulonglong2*)&wl[l][c4 * 4];
        ulonglong2 w1 = *(ulonglong2*)&wl[l + 32][c4 * 4];
        ulonglong2 w2 = *(ulonglong2*)&wr[l][c4 * 4];
        ulonglong2 w3 = *(ulonglong2*)&wr[l + 32][c4 * 4];
        #pragma unroll
        for (int nn = 0; nn < 8; nn++) {
            ulonglong2 xv = *(ulonglong2*)(xs + (ng * 8 + nn) * 64 + c4 * 4);
            fma2(az0[nn], xv.x, w0.x); fma2(az0[nn], xv.y, w0.y);
            fma2(az1[nn], xv.x, w1.x); fma2(az1[nn], xv.y, w1.y);
            fma2(ay0[nn], xv.x, w2.x); fma2(ay0[nn], xv.y, w2.y);
            fma2(ay1[nn], xv.x, w3.x); fma2(ay1[nn], xv.y, w3.y);
        }
    }
    #pragma unroll
    for (int nn = 0; nn < 8; nn++) {
        int gg = (base + ng * 8 + nn) * 64;
        g_z[gg + l]      = pairsum(az0[nn]);
        g_z[gg + l + 32] = pairsum(az1[nn]);
        g_y[gg + l]      = pairsum(ay0[nn]) + bll;
        g_y[gg + l + 32] = pairsum(ay1[nn]) + blh;
    }
}

// ---------------------------------------------------------------------------
// Kernel 2: HMMA distances + filtered-append top-9.
// 512 thr, grid 128. Iter 0 bootstraps per-row thresholds via stripe chains;
// iters 1-7 producers append (w,idx) keys above row threshold to per-row
// buffers; 64 row-threads maintain exact sorted-9 (u64 keys; tie->lower idx).
// ---------------------------------------------------------------------------
#define OFF_A    0           // 18432
#define OFF_B    18432       // 2 x 36864 -> end 92160
#define OFF_DIST 92160       // single buf [2img][64][68] = 34816 -> 126976
#define OFF_SQJ  126976      // 4096 -> 131072
#define OFF_THR  131072      // 64 u32 -> 131328
#define OFF_CNTA 131328      // 64x2 int -> 131840
#define OFF_SCNT 131840      // 256 -> 132096
#define OFF_SEL  132096      // 2304 -> 134400
#define OFF_BUF  134400      // 64 rows x 2 halves x 48 x u64 = 49152 -> 183552
#define OFF_KD   183552      // 512 lists x 9 x u64 = 36864 -> 220416
#define K_SMEM   220416

__device__ __forceinline__ float4 f4add(float4 a, float4 b) {
    return make_float4(a.x + b.x, a.y + b.y, a.z + b.z, a.w + b.w);
}
__device__ __forceinline__ float4 f4madd(float4 a, float s, float4 b) {
    return make_float4(fmaf(a.x, s, b.x), fmaf(a.y, s, b.y),
                       fmaf(a.z, s, b.z), fmaf(a.w, s, b.w));
}

__device__ __forceinline__ void prefetch_j128(u32t dstbase, int jt, int t) {
    #pragma unroll
    for (int k = 0; k < 4; k++) {
        int idx = k * 512 + t;
        int img = idx >> 10, rem = idx & 1023;
        int sp = rem >> 9, r3 = rem & 511;
        int row = r3 >> 3, c = r3 & 7;
        const uint4* src = (sp ? g_m16 : g_h16) + ((jt + img) * 64 + row) * 8 + c;
        cpa16(dstbase + img * 18432 + sp * 9216 + row * 144 + c * 16, src);
    }
}

__global__ void __launch_bounds__(512, 1)
k_knn(float* __restrict__ out) {
    extern __shared__ char sm[];
    u32t sb = smem_u32(sm);
    float* dist = (float*)(sm + OFF_DIST);
    float* sqj  = (float*)(sm + OFF_SQJ);
    u32t*  thru = (u32t*)(sm + OFF_THR);
    int*   cnta = (int*)(sm + OFF_CNTA);
    int*   scnt = (int*)(sm + OFF_SCNT);
    int*   sel  = (int*)(sm + OFF_SEL);
    u64t*  bufk = (u64t*)(sm + OFF_BUF);
    u64t*  KD   = (u64t*)(sm + OFF_KD);

    int t = threadIdx.x;
    int warp = t >> 5, lane = t & 31;
    int i0 = blockIdx.x * 64;
    int b = batch_of(i0);
    int jt0 = b << 4;
    bool spc = (b == 7);

    int iown = t & 63, q = t >> 6;

    // initial loads: A image, sqj, B window 0
    #pragma unroll
    for (int k = 0; k < 2; k++) {
        int idx = k * 512 + t;
        int sp = idx >> 9, rem = idx & 511;
        int row = rem >> 3, c = rem & 7;
        const uint4* src = (sp ? g_m16 : g_h16) + (blockIdx.x * 64 + row) * 8 + c;
        cpa16(sb + OFF_A + sp * 9216 + row * 144 + c * 16, src);
    }
    if (t < 256) cpa16(sb + OFF_SQJ + t * 16, g_sq4 + (b << 8) + t);
    prefetch_j128(sb + OFF_B, jt0, t);
    CPA_COMMIT();
    CPA_WAIT0();
    __syncthreads();

    int m0 = (warp & 3) * 16;
    int nwin = (warp >> 2) * 16;
    int cb = nwin + (lane & 3) * 2;
    int r0l = m0 + (lane >> 2);
    u32t Ah[4][4], Am[4][4];
    {
        u32t abase = sb + (m0 + (lane & 15)) * 144 + (lane >> 4) * 16;
        #pragma unroll
        for (int k = 0; k < 4; k++) {
            ldsm4(Ah[k], abase + OFF_A + k * 32);
            ldsm4(Am[k], abase + OFF_A + 9216 + k * 32);
        }
    }

    u32t boff = ((lane >> 4) * 8 + (lane & 7)) * 144 + ((lane >> 3) & 1) * 16;

    u64t S[9];                      // row-thread sorted-9 (t<64 only meaningful)
    #pragma unroll
    for (int k = 0; k < KNN; k++) S[k] = 0ull;

    // =================== iteration 0 (bootstrap) ===================
    prefetch_j128(sb + OFF_B + 36864, jt0 + 2, t);   // B for iter 1
    CPA_COMMIT();
    {
        float C[2][2][4];
        #pragma unroll
        for (int img = 0; img < 2; img++)
            #pragma unroll
            for (int nb = 0; nb < 2; nb++)
                #pragma unroll
                for (int e = 0; e < 4; e++) C[img][nb][e] = 0.f;
        #pragma unroll
        for (int img = 0; img < 2; img++) {
            u32t hb = sb + OFF_B + img * 18432 + nwin * 144 + boff;
            u32t mb = hb + 9216;
            #pragma unroll
            for (int k = 0; k < 4; k++) {
                u32t bh[4], bm[4];
                ldsm4(bh, hb + k * 32);
                ldsm4(bm, mb + k * 32);
                mma16816(C[img][0], Ah[k], &bh[0]);
                mma16816(C[img][1], Ah[k], &bh[2]);
                mma16816(C[img][0], Am[k], &bh[0]);
                mma16816(C[img][1], Am[k], &bh[2]);
                mma16816(C[img][0], Ah[k], &bm[0]);
                mma16816(C[img][1], Ah[k], &bm[2]);
            }
        }
        // w = 2*dot - sqj, store to dist (single buffer)
        #pragma unroll
        for (int img = 0; img < 2; img++) {
            #pragma unroll
            for (int nb = 0; nb < 2; nb++) {
                float2 sj = *(const float2*)(sqj + img * 64 + cb + nb * 8);
                float* dp = dist + img * 4352;
                *(float2*)(dp + r0l * 68 + cb + nb * 8) =
                    make_float2(fmaf(2.f, C[img][nb][0], -sj.x),
                                fmaf(2.f, C[img][nb][1], -sj.y));
                *(float2*)(dp + (r0l + 8) * 68 + cb + nb * 8) =
                    make_float2(fmaf(2.f, C[img][nb][2], -sj.x),
                                fmaf(2.f, C[img][nb][3], -sj.y));
            }
        }
    }
    __syncthreads();

    // stripe select of iter-0 (all 512 threads, u64 keys)
    {
        u64t L[9];
        #pragma unroll
        for (int k = 0; k < KNN; k++) L[k] = 0ull;
        const float* drow = dist + (q >> 2) * 4352 + iown * 68 + (q & 3) * 16;
        bool maskall = (i0 + iown) == 8191;
        int j0 = (b << 10) + q * 16;
        float4 d0 = *(const float4*)(drow + 0);
        float4 d1 = *(const float4*)(drow + 4);
        float4 d2 = *(const float4*)(drow + 8);
        float4 d3 = *(const float4*)(drow + 12);
        float dv[16] = {d0.x, d0.y, d0.z, d0.w, d1.x, d1.y, d1.z, d1.w,
                        d2.x, d2.y, d2.z, d2.w, d3.x, d3.y, d3.z, d3.w};
        #pragma unroll
        for (int k = 0; k < 16; k++) {
            u32t u = maskall ? 0u : fsort(dv[k]);
            u64t key = ((u64t)u << 32) | (u32t)~(j0 + k);
            if (key > L[KNN - 1]) {
                u64t nk = key;
                #pragma unroll
                for (int s = 0; s < KNN; s++) {
                    bool gt = nk > L[s];
                    u64t tv = L[s];
                    L[s] = gt ? nk : L[s];
                    nk = gt ? tv : nk;
                }
            }
        }
        #pragma unroll
        for (int k = 0; k < KNN; k++) KD[(iown * 8 + q) * KNN + k] = L[k];
    }
    __syncthreads();

    // row-threads: 8-way merge -> S, init thresholds; init counters
    if (t < 64) {
        int ptr8[8] = {0, 0, 0, 0, 0, 0, 0, 0};
        #pragma unroll
        for (int k = 0; k < KNN; k++) {
            u64t bk = 0ull; int bl = 0;
            #pragma unroll
            for (int l = 0; l < 8; l++) {
                u64t cand = KD[(t * 8 + l) * KNN + ptr8[l]];
                bool tk = cand > bk;
                bk = tk ? cand : bk;
                bl = tk ? l : bl;
            }
            ptr8[bl]++;
            S[k] = bk;
        }
        bool r8 = (i0 + t) == 8191;
        thru[t] = r8 ? 0xffffffffu : (u32t)(S[KNN - 1] >> 32);
    }
    if (t < 128) cnta[t] = 0;
    __syncthreads();

    // =================== iterations 1..7 ===================
    #pragma unroll 1
    for (int it = 1; it < 8; it++) {
        if (it < 7)
            prefetch_j128(sb + OFF_B + ((it + 1) & 1) * 36864, jt0 + 2 * (it + 1), t);
        CPA_COMMIT();

        // row-duty: fold in appends from iter it-1 (half (it-1)&1), bump thr
        if (t < 64) {
            int half = (it - 1) & 1;
            int n = cnta[t * 2 + half];
            n = n > 48 ? 48 : n;
            for (int e = 0; e < n; e++) {
                u64t key = bufk[(t * 2 + half) * 48 + e];
                if (key > S[KNN - 1]) {
                    u64t nk = key;
                    #pragma unroll
                    for (int s = 0; s < KNN; s++) {
                        bool gt = nk > S[s];
                        u64t tv = S[s];
                        S[s] = gt ? nk : S[s];
                        nk = gt ? tv : nk;
                    }
                }
            }
            cnta[t * 2 + half] = 0;
            if ((i0 + t) != 8191) thru[t] = (u32t)(S[KNN - 1] >> 32);
        }

        u32t bufb = sb + OFF_B + (it & 1) * 36864;
        float C[2][2][4];
        #pragma unroll
        for (int img = 0; img < 2; img++)
            #pragma unroll
            for (int nb = 0; nb < 2; nb++)
                #pragma unroll
                for (int e = 0; e < 4; e++) C[img][nb][e] = 0.f;

        #pragma unroll
        for (int img = 0; img < 2; img++) {
            u32t hb = bufb + img * 18432 + nwin * 144 + boff;
            u32t mb = hb + 9216;
            #pragma unroll
            for (int k = 0; k < 4; k++) {
                u32t bh[4], bm[4];
                ldsm4(bh, hb + k * 32);
                ldsm4(bm, mb + k * 32);
                mma16816(C[img][0], Ah[k], &bh[0]);
                mma16816(C[img][1], Ah[k], &bh[2]);
                mma16816(C[img][0], Am[k], &bh[0]);
                mma16816(C[img][1], Am[k], &bh[2]);
                mma16816(C[img][0], Ah[k], &bm[0]);
                mma16816(C[img][1], Ah[k], &bm[2]);
            }
        }

        // w + filtered append (half it&1)
        {
            float w[2][2][4];
            float wmax = f_ninf();
            #pragma unroll
            for (int img = 0; img < 2; img++)
                #pragma unroll
                for (int nb = 0; nb < 2; nb++) {
                    float2 sj = *(const float2*)(sqj + it * 128 + img * 64 + cb + nb * 8);
                    w[img][nb][0] = fmaf(2.f, C[img][nb][0], -sj.x);
                    w[img][nb][1] = fmaf(2.f, C[img][nb][1], -sj.y);
                    w[img][nb][2] = fmaf(2.f, C[img][nb][2], -sj.x);
                    w[img][nb][3] = fmaf(2.f, C[img][nb][3], -sj.y);
                    #pragma unroll
                    for (int e = 0; e < 4; e++) wmax = fmaxf(wmax, w[img][nb][e]);
                }
            u32t thr0 = thru[r0l];
            u32t thr1 = thru[r0l + 8];
            u32t thmin = thr0 < thr1 ? thr0 : thr1;
            bool kill = spc && (it == 7) && (cb == 54);
            if (fsort(wmax) > thmin) {
                int half = it & 1;
                #pragma unroll
                for (int img = 0; img < 2; img++)
                    #pragma unroll
                    for (int nb = 0; nb < 2; nb++)
                        #pragma unroll
                        for (int e = 0; e < 4; e++) {
                            int colg = (b << 10) + it * 128 + img * 64 + cb + nb * 8 + (e & 1);
                            int rowl = (e < 2) ? r0l : (r0l + 8);
                            u32t th = (e < 2) ? thr0 : thr1;
                            bool mk = kill && (img == 1) && (nb == 1) && ((e & 1) == 1);
                            u32t u = fsort(w[img][nb][e]);
                            if (!mk && u > th) {
                                int pos = atomicAdd(&cnta[rowl * 2 + half], 1);
                                if (pos < 48)
                                    bufk[(rowl * 2 + half) * 48 + pos] =
                                        ((u64t)u << 32) | (u32t)~colg;
                            }
                        }
            }
        }
        CPA_WAIT0();
        __syncthreads();
    }

    // final row-duty: fold iter-7 appends (half 1), emit sel/scnt
    if (t < 64) {
        int n = cnta[t * 2 + 1];
        n = n > 48 ? 48 : n;
        for (int e = 0; e < n; e++) {
            u64t key = bufk[(t * 2 + 1) * 48 + e];
            if (key > S[KNN - 1]) {
                u64t nk = key;
                #pragma unroll
                for (int s = 0; s < KNN; s++) {
                    bool gt = nk > S[s];
                    u64t tv = S[s];
                    S[s] = gt ? nk : S[s];
                    nk = gt ? tv : nk;
                }
            }
        }
        int cnt = 0;
        #pragma unroll
        for (int k = 0; k < KNN; k++) {
            sel[t * KNN + k] = ~((u32t)S[k]);
            cnt += ((u32t)(S[k] >> 32)) > 0x007fffffu;
        }
        if (cnt == 0) { sel[t * KNN] = i0 + t; cnt = 1; }
        scnt[t] = cnt;
    }
    __syncthreads();

    // epilogue: 8 threads/node x 8 channels
    int ie = t >> 3, part = t & 7;
    int gi = i0 + ie;
    float4 a0 = {0,0,0,0}, a1 = {0,0,0,0};
    int cnt = scnt[ie];
    for (int k = 0; k < cnt; k++) {
        const float4* zr = (const float4*)(g_z + sel[ie * KNN + k] * 64 + part * 8);
        a0 = f4add(a0, zr[0]);
        a1 = f4add(a1, zr[1]);
    }
    float inv = 1.0f / (float)cnt;
    const float4* yr = (const float4*)(g_y + gi * 64 + part * 8);
    float4* op = (float4*)(out + gi * 64 + part * 8);
    op[0] = f4madd(a0, inv, yr[0]);
    op[1] = f4madd(a1, inv, yr[1]);
}

// ---------------------------------------------------------------------------
extern "C" void kernel_launch(void* const* d_in, const int* in_sizes, int n_in,
                              void* d_out, int out_size) {
    (void)in_sizes; (void)n_in; (void)out_size;
    const float* x  = (const float*)d_in[0];
    const float* Wl = (const float*)d_in[1];
    const float* bl = (const float*)d_in[2];
    const float* Wr = (const float*)d_in[3];
    float* out = (float*)d_out;

    cudaFuncSetAttribute(k_pg,  cudaFuncAttributeMaxDynamicSharedMemorySize, PG_SMEM);
    cudaFuncSetAttribute(k_knn, cudaFuncAttributeMaxDynamicSharedMemorySize, K_SMEM);

    k_pg<<<128, 256, PG_SMEM>>>(x, Wl, bl, Wr);
    k_knn<<<128, 512, K_SMEM>>>(out);
}